// round 13
// baseline (speedup 1.0000x reference)
#include <cuda_runtime.h>
#include <cstdint>

// Problem constants
#define BB    8
#define C     128
#define W     256
#define H     256
#define NPIX  (W*H)          // 65536 pixels per image
#define NSEG  16             // segments per channel in k_cent
#define NCB   (C * NSEG)     // 2048 k_cent blocks

// Output buffer layout (concatenated f32, raw reshapes):
#define OFF_CENTERS 0
#define OFF_LABELS  256
#define OFF_ONEHOT  (OFF_LABELS + BB*NPIX)
#define OFF_DIST    (OFF_ONEHOT + BB*2*NPIX)
#define OFF_LABELT  (OFF_DIST   + BB*2*NPIX)

// Scratch (__device__ globals; overwrite-slot semantics, counter self-resets).
// g_mask: batch-7 labels as bits. For float4 index j (0..16383):
//   word = g_mask[j>>5], lane = j&31, label(pixel 4j+c) = bit lane of comp c.
__device__ uint4 g_mask[512];
// g_part[(k*128+ch)*NSEG + seg]
__device__ float g_part[256 * NSEG];
__device__ int   g_arrive = 0;

// ---------------------------------------------------------------------------
// Kernel 1: the proven roofline main pass (unchanged).
// ---------------------------------------------------------------------------
__global__ void __launch_bounds__(256) k_main(const float* __restrict__ F,
                                              const float* __restrict__ Cinit,
                                              float* __restrict__ out) {
    __shared__ float sc[2*C];
    int t = threadIdx.x;
    sc[t] = Cinit[t];
    __syncthreads();

    int blk  = blockIdx.x;
    int b    = blk >> 6;
    int slot = blk & 63;
    int p4   = slot * 256 + t;
    int n0   = p4 << 2;
    bool is7 = (b == BB - 1);

    const float4* Fb = reinterpret_cast<const float4*>(F + (size_t)b * C * NPIX);

    float4 a0 = make_float4(0.f,0.f,0.f,0.f);
    float4 a1 = make_float4(0.f,0.f,0.f,0.f);
    if (is7) {
        #pragma unroll 8
        for (int ch = 0; ch < C; ch++) {
            float4 f = Fb[ch * (NPIX/4) + p4];
            float c0 = sc[ch], c1 = sc[C + ch];
            a0.x += f.x*c0; a0.y += f.y*c0; a0.z += f.z*c0; a0.w += f.w*c0;
            a1.x += f.x*c1; a1.y += f.y*c1; a1.z += f.z*c1; a1.w += f.w*c1;
        }
    } else {
        #pragma unroll 8
        for (int ch = 0; ch < C; ch++) {
            float4 f = __ldcs(&Fb[ch * (NPIX/4) + p4]);
            float c0 = sc[ch], c1 = sc[C + ch];
            a0.x += f.x*c0; a0.y += f.y*c0; a0.z += f.z*c0; a0.w += f.w*c0;
            a1.x += f.x*c1; a1.y += f.y*c1; a1.z += f.z*c1; a1.w += f.w*c1;
        }
    }

    float d0x = 0.5f - 0.5f*a0.x, d1x = 0.5f - 0.5f*a1.x;
    float d0y = 0.5f - 0.5f*a0.y, d1y = 0.5f - 0.5f*a1.y;
    float d0z = 0.5f - 0.5f*a0.z, d1z = 0.5f - 0.5f*a1.z;
    float d0w = 0.5f - 0.5f*a0.w, d1w = 0.5f - 0.5f*a1.w;

    int lx = d1x < d0x, ly = d1y < d0y, lz = d1z < d0z, lw = d1w < d0w;
    float4 lab = make_float4((float)lx, (float)ly, (float)lz, (float)lw);

    __stcs(reinterpret_cast<float4*>(out + OFF_LABELS + (size_t)b*NPIX + n0), lab);
    __stcs(reinterpret_cast<float4*>(out + OFF_LABELT + (size_t)b*NPIX + n0), lab);

    float4* outO = reinterpret_cast<float4*>(out + OFF_ONEHOT + (size_t)b*2*NPIX + 2*n0);
    __stcs(outO + 0, make_float4(1.f - lab.x, lab.x, 1.f - lab.y, lab.y));
    __stcs(outO + 1, make_float4(1.f - lab.z, lab.z, 1.f - lab.w, lab.w));

    float4* outD = reinterpret_cast<float4*>(out + OFF_DIST + (size_t)b*2*NPIX + 2*n0);
    __stcs(outD + 0, make_float4(d0x, d1x, d0y, d1y));
    __stcs(outD + 1, make_float4(d0z, d1z, d0w, d1w));

    if (is7) {
        unsigned bx = __ballot_sync(0xffffffffu, lx);
        unsigned by = __ballot_sync(0xffffffffu, ly);
        unsigned bz = __ballot_sync(0xffffffffu, lz);
        unsigned bw = __ballot_sync(0xffffffffu, lw);
        if ((t & 31) == 0) g_mask[p4 >> 5] = make_uint4(bx, by, bz, bw);
    }
}

// ---------------------------------------------------------------------------
// Kernel 2: phase-2, occupancy/MLP-fixed.
// Grid 2048 x 256: ch = blk&127, seg = blk>>7 (16 segs x 1024 f4 = 16KB each).
// All 4 float4 + 4 mask words loaded up-front (front-batched LDGs, MLP>=8),
// then accumulated. ~8 blocks/SM resident -> latency fully hidden.
// Last-arriving block: popcount + centers epilogue; counter self-resets.
// ---------------------------------------------------------------------------
__global__ void __launch_bounds__(256) k_cent(const float* __restrict__ F,
                                              const float* __restrict__ Cinit,
                                              float* __restrict__ out) {
    __shared__ float wa[8], w1[8];
    __shared__ int   wc[8];
    __shared__ int   s_done, s_cnt;

    int t    = threadIdx.x;
    int lane = t & 31;
    int wid  = t >> 5;
    int blk  = blockIdx.x;
    int ch   = blk & 127;
    int seg  = blk >> 7;               // 0..15

    const float4* Fp = reinterpret_cast<const float4*>(
        F + ((size_t)(BB-1) * C + ch) * NPIX);
    int base = seg * 1024;             // f4 index base (4096 px per seg)

    // front-batched loads: 4 float4 + 4 mask words, all independent
    float4 f0 = Fp[base +   0 + t];
    float4 f1 = Fp[base + 256 + t];
    float4 f2 = Fp[base + 512 + t];
    float4 f3 = Fp[base + 768 + t];
    uint4  m0 = g_mask[(base +   0 + t) >> 5];
    uint4  m1 = g_mask[(base + 256 + t) >> 5];
    uint4  m2 = g_mask[(base + 512 + t) >> 5];
    uint4  m3 = g_mask[(base + 768 + t) >> 5];

    float sa0, sa1, s1a, s1b;
    sa0 = f0.x + f0.y + f0.z + f0.w + f1.x + f1.y + f1.z + f1.w;
    sa1 = f2.x + f2.y + f2.z + f2.w + f3.x + f3.y + f3.z + f3.w;
    s1a = f0.x*(float)((m0.x >> lane)&1u) + f0.y*(float)((m0.y >> lane)&1u)
        + f0.z*(float)((m0.z >> lane)&1u) + f0.w*(float)((m0.w >> lane)&1u)
        + f1.x*(float)((m1.x >> lane)&1u) + f1.y*(float)((m1.y >> lane)&1u)
        + f1.z*(float)((m1.z >> lane)&1u) + f1.w*(float)((m1.w >> lane)&1u);
    s1b = f2.x*(float)((m2.x >> lane)&1u) + f2.y*(float)((m2.y >> lane)&1u)
        + f2.z*(float)((m2.z >> lane)&1u) + f2.w*(float)((m2.w >> lane)&1u)
        + f3.x*(float)((m3.x >> lane)&1u) + f3.y*(float)((m3.y >> lane)&1u)
        + f3.z*(float)((m3.z >> lane)&1u) + f3.w*(float)((m3.w >> lane)&1u);

    float sa = sa0 + sa1;
    float s1 = s1a + s1b;

    #pragma unroll
    for (int o = 16; o > 0; o >>= 1) {
        sa += __shfl_down_sync(0xffffffffu, sa, o);
        s1 += __shfl_down_sync(0xffffffffu, s1, o);
    }
    if (lane == 0) { wa[wid] = sa; w1[wid] = s1; }
    __syncthreads();
    if (t == 0) {
        float va = 0.f, v1 = 0.f;
        #pragma unroll
        for (int i = 0; i < 8; i++) { va += wa[i]; v1 += w1[i]; }
        g_part[(ch)     * NSEG + seg] = va - v1;   // label 0 sum
        g_part[(C + ch) * NSEG + seg] = v1;        // label 1 sum
    }

    // ---- arrival; last block does the epilogue ----
    __syncthreads();
    if (t == 0) {
        __threadfence();
        int old = atomicAdd(&g_arrive, 1);
        s_done = (old == NCB - 1);
    }
    __syncthreads();
    if (!s_done) return;
    __threadfence();

    // label-1 count via mask popcount (512 uint4 / 256 threads = 2 each)
    {
        uint4 q0 = g_mask[2*t], q1 = g_mask[2*t + 1];
        int c = __popc(q0.x) + __popc(q0.y) + __popc(q0.z) + __popc(q0.w)
              + __popc(q1.x) + __popc(q1.y) + __popc(q1.z) + __popc(q1.w);
        #pragma unroll
        for (int o = 16; o > 0; o >>= 1)
            c += __shfl_down_sync(0xffffffffu, c, o);
        if (lane == 0) wc[wid] = c;
        __syncthreads();
        if (t == 0) {
            int v = 0;
            #pragma unroll
            for (int i = 0; i < 8; i++) v += wc[i];
            s_cnt = v;
        }
        __syncthreads();
    }

    float sum = 0.f;
    #pragma unroll
    for (int i = 0; i < NSEG; i++) sum += __ldcg(&g_part[t*NSEG + i]);

    int k = t >> 7;
    float num = (k ? (float)s_cnt : (float)(NPIX - s_cnt)) + 1.0f;
    float mean = sum / num;
    float ci = Cinit[t];
    out[OFF_CENTERS + t] = ci + 0.001f * (mean - ci);

    if (t == 0) g_arrive = 0;          // reset for next graph replay
}

// ---------------------------------------------------------------------------
extern "C" void kernel_launch(void* const* d_in, const int* in_sizes, int n_in,
                              void* d_out, int out_size) {
    const float* F     = (const float*)d_in[0];   // FeatureT [8,128,256,256]
    const float* Cinit = (const float*)d_in[1];   // centerInit [2,128]
    float* out = (float*)d_out;
    (void)in_sizes; (void)n_in; (void)out_size;

    k_main<<<512, 256>>>(F, Cinit, out);
    k_cent<<<NCB, 256>>>(F, Cinit, out);
}

// round 14
// speedup vs baseline: 1.0818x; 1.0818x over previous
#include <cuda_runtime.h>
#include <cstdint>

// Problem constants
#define BB    8
#define C     128
#define W     256
#define H     256
#define NPIX  (W*H)          // 65536 pixels per image
#define NBLK  512            // grid size; all co-resident (one wave)
#define NB7   64             // blocks owning batch 7

// Output buffer layout (concatenated f32, raw reshapes):
#define OFF_CENTERS 0
#define OFF_LABELS  256
#define OFF_ONEHOT  (OFF_LABELS + BB*NPIX)
#define OFF_DIST    (OFF_ONEHOT + BB*2*NPIX)
#define OFF_LABELT  (OFF_DIST   + BB*2*NPIX)

// Scratch (__device__ globals; overwrite-slot semantics, counters self-reset).
// g_mask: batch-7 labels as bits. For float4 index j (0..16383):
//   word = g_mask[j>>5], lane = j&31, label(pixel 4j+c) = bit lane of comp c.
__device__ uint4 g_mask[512];
// g_part[(k*128+ch)*4 + seg]: per-segment per-channel label-k sums (batch 7)
__device__ float g_part[256 * 4];
__device__ int   g_ready  = 0;   // # b7 blocks that published their mask
__device__ int   g_arrive = 0;   // phase-2 arrival counter

// ---------------------------------------------------------------------------
// Single kernel, 512 blocks x 256 threads, one wave via __launch_bounds__(256,4).
// Phase 1: per-block main tile (R6, unchanged — proven 7.4TB/s geometry).
// Phase 2: cooperative F7 masked channel sums — NOW with explicit 4-wide
//          front-batched float4 loads (reg-resident, MLP>=4) and the mask
//          staged in smem. This is the only change vs the 45.1us R6 kernel.
// Epilogue: last-arriving block; counters self-reset for graph replay.
// ---------------------------------------------------------------------------
__global__ void __launch_bounds__(256, 4)
k_all(const float* __restrict__ F,
      const float* __restrict__ Cinit,
      float* __restrict__ out) {
    __shared__ float sc[2*C];
    __shared__ uint4 smask[128];    // mask words for this block's segment
    __shared__ float wa[8], w1[8];
    __shared__ int   wc[8];
    __shared__ int   s_done, s_cnt;

    int t = threadIdx.x;
    sc[t] = Cinit[t];
    __syncthreads();

    int blk  = blockIdx.x;             // 0..511
    int b    = blk >> 6;               // batch 0..7
    int slot = blk & 63;
    int p4   = slot * 256 + t;         // float4-pixel index within image
    int n0   = p4 << 2;
    int wid  = t >> 5, lane = t & 31;
    bool is7 = (b == BB - 1);

    // ---------------- Phase 1: main pass (unchanged from R6) ----------------
    {
        const float4* Fb = reinterpret_cast<const float4*>(F + (size_t)b * C * NPIX);
        float4 a0 = make_float4(0.f,0.f,0.f,0.f);
        float4 a1 = make_float4(0.f,0.f,0.f,0.f);
        if (is7) {
            #pragma unroll 8
            for (int ch = 0; ch < C; ch++) {
                float4 f = Fb[ch * (NPIX/4) + p4];
                float c0 = sc[ch], c1 = sc[C + ch];
                a0.x += f.x*c0; a0.y += f.y*c0; a0.z += f.z*c0; a0.w += f.w*c0;
                a1.x += f.x*c1; a1.y += f.y*c1; a1.z += f.z*c1; a1.w += f.w*c1;
            }
        } else {
            #pragma unroll 8
            for (int ch = 0; ch < C; ch++) {
                float4 f = __ldcs(&Fb[ch * (NPIX/4) + p4]);
                float c0 = sc[ch], c1 = sc[C + ch];
                a0.x += f.x*c0; a0.y += f.y*c0; a0.z += f.z*c0; a0.w += f.w*c0;
                a1.x += f.x*c1; a1.y += f.y*c1; a1.z += f.z*c1; a1.w += f.w*c1;
            }
        }

        float d0x = 0.5f - 0.5f*a0.x, d1x = 0.5f - 0.5f*a1.x;
        float d0y = 0.5f - 0.5f*a0.y, d1y = 0.5f - 0.5f*a1.y;
        float d0z = 0.5f - 0.5f*a0.z, d1z = 0.5f - 0.5f*a1.z;
        float d0w = 0.5f - 0.5f*a0.w, d1w = 0.5f - 0.5f*a1.w;

        int lx = d1x < d0x, ly = d1y < d0y, lz = d1z < d0z, lw = d1w < d0w;
        float4 lab = make_float4((float)lx, (float)ly, (float)lz, (float)lw);

        __stcs(reinterpret_cast<float4*>(out + OFF_LABELS + (size_t)b*NPIX + n0), lab);
        __stcs(reinterpret_cast<float4*>(out + OFF_LABELT + (size_t)b*NPIX + n0), lab);

        float4* outO = reinterpret_cast<float4*>(out + OFF_ONEHOT + (size_t)b*2*NPIX + 2*n0);
        __stcs(outO + 0, make_float4(1.f - lab.x, lab.x, 1.f - lab.y, lab.y));
        __stcs(outO + 1, make_float4(1.f - lab.z, lab.z, 1.f - lab.w, lab.w));

        float4* outD = reinterpret_cast<float4*>(out + OFF_DIST + (size_t)b*2*NPIX + 2*n0);
        __stcs(outD + 0, make_float4(d0x, d1x, d0y, d1y));
        __stcs(outD + 1, make_float4(d0z, d1z, d0w, d1w));

        if (is7) {
            unsigned bx = __ballot_sync(0xffffffffu, lx);
            unsigned by = __ballot_sync(0xffffffffu, ly);
            unsigned bz = __ballot_sync(0xffffffffu, lz);
            unsigned bw = __ballot_sync(0xffffffffu, lw);
            if (lane == 0) g_mask[p4 >> 5] = make_uint4(bx, by, bz, bw);
            __syncthreads();
            if (t == 0) {
                __threadfence();             // publish mask
                atomicAdd(&g_ready, 1);      // release
            }
        }
    }

    // ---------------- Phase 2: cooperative F7 masked channel sums ----------
    // Chunk: channel ch = blk & 127, segment seg = blk >> 7 (4096 f4 each).
    int ch  = blk & 127;
    int seg = blk >> 7;                    // 0..3

    if (t == 0) {                          // wait for full mask (one wave)
        volatile int* r = &g_ready;
        while (*r < NB7) __nanosleep(128);
    }
    __syncthreads();
    __threadfence();                       // acquire mask

    // stage this segment's 128 mask words into smem (2KB)
    if (t < 128) smask[t] = g_mask[seg * 128 + t];
    __syncthreads();

    const float4* Fp = reinterpret_cast<const float4*>(
        F + ((size_t)(BB-1) * C + ch) * NPIX) + seg * 4096;

    float sa = 0.f, s1 = 0.f;
    #pragma unroll
    for (int g = 0; g < 4; g++) {
        // 4 independent reg-resident loads (16 regs) -> front-batched LDGs
        float4 f0 = Fp[g*1024 +   0 + t];
        float4 f1 = Fp[g*1024 + 256 + t];
        float4 f2 = Fp[g*1024 + 512 + t];
        float4 f3 = Fp[g*1024 + 768 + t];
        uint4  m0 = smask[(g*1024 +   0 + t) >> 5];
        uint4  m1 = smask[(g*1024 + 256 + t) >> 5];
        uint4  m2 = smask[(g*1024 + 512 + t) >> 5];
        uint4  m3 = smask[(g*1024 + 768 + t) >> 5];

        sa += f0.x + f0.y + f0.z + f0.w + f1.x + f1.y + f1.z + f1.w
            + f2.x + f2.y + f2.z + f2.w + f3.x + f3.y + f3.z + f3.w;
        s1 += f0.x*(float)((m0.x >> lane)&1u) + f0.y*(float)((m0.y >> lane)&1u)
            + f0.z*(float)((m0.z >> lane)&1u) + f0.w*(float)((m0.w >> lane)&1u)
            + f1.x*(float)((m1.x >> lane)&1u) + f1.y*(float)((m1.y >> lane)&1u)
            + f1.z*(float)((m1.z >> lane)&1u) + f1.w*(float)((m1.w >> lane)&1u)
            + f2.x*(float)((m2.x >> lane)&1u) + f2.y*(float)((m2.y >> lane)&1u)
            + f2.z*(float)((m2.z >> lane)&1u) + f2.w*(float)((m2.w >> lane)&1u)
            + f3.x*(float)((m3.x >> lane)&1u) + f3.y*(float)((m3.y >> lane)&1u)
            + f3.z*(float)((m3.z >> lane)&1u) + f3.w*(float)((m3.w >> lane)&1u);
    }
    #pragma unroll
    for (int o = 16; o > 0; o >>= 1) {
        sa += __shfl_down_sync(0xffffffffu, sa, o);
        s1 += __shfl_down_sync(0xffffffffu, s1, o);
    }
    if (lane == 0) { wa[wid] = sa; w1[wid] = s1; }
    __syncthreads();
    if (t == 0) {
        float va = 0.f, v1 = 0.f;
        #pragma unroll
        for (int i = 0; i < 8; i++) { va += wa[i]; v1 += w1[i]; }
        g_part[(ch)     * 4 + seg] = va - v1;   // label 0 sum
        g_part[(C + ch) * 4 + seg] = v1;        // label 1 sum
    }

    // ---------------- arrival; last block does the epilogue ----------------
    __syncthreads();
    if (t == 0) {
        __threadfence();
        int old = atomicAdd(&g_arrive, 1);
        s_done = (old == NBLK - 1);
    }
    __syncthreads();
    if (!s_done) return;
    __threadfence();

    // label-1 count via mask popcount (512 uint4 / 256 threads = 2 each)
    {
        uint4 m0 = g_mask[2*t], m1 = g_mask[2*t + 1];
        int c = __popc(m0.x) + __popc(m0.y) + __popc(m0.z) + __popc(m0.w)
              + __popc(m1.x) + __popc(m1.y) + __popc(m1.z) + __popc(m1.w);
        #pragma unroll
        for (int o = 16; o > 0; o >>= 1)
            c += __shfl_down_sync(0xffffffffu, c, o);
        if (lane == 0) wc[wid] = c;
        __syncthreads();
        if (t == 0) {
            int v = 0;
            #pragma unroll
            for (int i = 0; i < 8; i++) v += wc[i];
            s_cnt = v;
        }
        __syncthreads();
    }

    // reduce the 4 seg slots per (k,ch) and write centersIterout
    float sum = 0.f;
    #pragma unroll
    for (int i = 0; i < 4; i++) sum += __ldcg(&g_part[t*4 + i]);

    int k = t >> 7;
    float num = (k ? (float)s_cnt : (float)(NPIX - s_cnt)) + 1.0f;
    float mean = sum / num;
    float ci = sc[t];
    out[OFF_CENTERS + t] = ci + 0.001f * (mean - ci);

    if (t == 0) { g_arrive = 0; g_ready = 0; }   // reset for next graph replay
}

// ---------------------------------------------------------------------------
extern "C" void kernel_launch(void* const* d_in, const int* in_sizes, int n_in,
                              void* d_out, int out_size) {
    const float* F     = (const float*)d_in[0];   // FeatureT [8,128,256,256]
    const float* Cinit = (const float*)d_in[1];   // centerInit [2,128]
    float* out = (float*)d_out;
    (void)in_sizes; (void)n_in; (void)out_size;

    k_all<<<NBLK, 256>>>(F, Cinit, out);
}

// round 15
// speedup vs baseline: 1.1848x; 1.0952x over previous
#include <cuda_runtime.h>
#include <cstdint>

// Problem constants
#define BB    8
#define C     128
#define W     256
#define H     256
#define NPIX  (W*H)          // 65536 pixels per image
#define NBLK  512            // one wave (4/SM x 148 = 592 slots)
#define NB7   64             // blocks owning batch 7

// Output buffer layout (concatenated f32, raw reshapes):
#define OFF_CENTERS 0
#define OFF_LABELS  256
#define OFF_ONEHOT  (OFF_LABELS + BB*NPIX)
#define OFF_DIST    (OFF_ONEHOT + BB*2*NPIX)
#define OFF_LABELT  (OFF_DIST   + BB*2*NPIX)

// Scratch (__device__ globals; overwrite-slot semantics, counters self-reset).
// g_mask: batch-7 labels as bits. For float4 index j (0..16383):
//   word = g_mask[j>>5], lane = j&31, label(pixel 4j+c) = bit lane of comp c.
__device__ uint4 g_mask[512];
// g_part[(k*128+ch)*4 + seg]
__device__ float g_part[256 * 4];
__device__ int   g_ready_seg[4] = {0,0,0,0};  // b7 publishes per segment (16 each)
__device__ int   g_arrive = 0;                // phase-2 arrival counter

// select f or 0 by mask bit -> FSEL/pred-FADD, no I2F
__device__ __forceinline__ float msel(unsigned m, int lane, float f) {
    return ((m >> lane) & 1u) ? f : 0.0f;
}

// ---------------------------------------------------------------------------
// Single kernel, 512 blocks x 256 threads (R6 structure).
// Phase 1: unchanged proven main pass; b7 publishes ballot mask + per-seg ready.
// Phase 2: cooperative masked channel sums; per-seg wait (16 producers only),
//          FSEL masking (no cvt), split accumulators.
// Epilogue: last-arriving block; counters self-reset for graph replay.
// ---------------------------------------------------------------------------
__global__ void __launch_bounds__(256, 4)
k_all(const float* __restrict__ F,
      const float* __restrict__ Cinit,
      float* __restrict__ out) {
    __shared__ float sc[2*C];
    __shared__ float wa[8], w1[8];
    __shared__ int   wc[8];
    __shared__ int   s_done, s_cnt;

    int t = threadIdx.x;
    sc[t] = Cinit[t];
    __syncthreads();

    int blk  = blockIdx.x;             // 0..511
    int b    = blk >> 6;               // batch 0..7
    int slot = blk & 63;
    int p4   = slot * 256 + t;         // float4-pixel index within image
    int n0   = p4 << 2;
    int wid  = t >> 5, lane = t & 31;
    bool is7 = (b == BB - 1);

    // ---------------- Phase 1: main pass (unchanged from R6) ----------------
    {
        const float4* Fb = reinterpret_cast<const float4*>(F + (size_t)b * C * NPIX);
        float4 a0 = make_float4(0.f,0.f,0.f,0.f);
        float4 a1 = make_float4(0.f,0.f,0.f,0.f);
        if (is7) {
            #pragma unroll 8
            for (int ch = 0; ch < C; ch++) {
                float4 f = Fb[ch * (NPIX/4) + p4];
                float c0 = sc[ch], c1 = sc[C + ch];
                a0.x += f.x*c0; a0.y += f.y*c0; a0.z += f.z*c0; a0.w += f.w*c0;
                a1.x += f.x*c1; a1.y += f.y*c1; a1.z += f.z*c1; a1.w += f.w*c1;
            }
        } else {
            #pragma unroll 8
            for (int ch = 0; ch < C; ch++) {
                float4 f = __ldcs(&Fb[ch * (NPIX/4) + p4]);
                float c0 = sc[ch], c1 = sc[C + ch];
                a0.x += f.x*c0; a0.y += f.y*c0; a0.z += f.z*c0; a0.w += f.w*c0;
                a1.x += f.x*c1; a1.y += f.y*c1; a1.z += f.z*c1; a1.w += f.w*c1;
            }
        }

        float d0x = 0.5f - 0.5f*a0.x, d1x = 0.5f - 0.5f*a1.x;
        float d0y = 0.5f - 0.5f*a0.y, d1y = 0.5f - 0.5f*a1.y;
        float d0z = 0.5f - 0.5f*a0.z, d1z = 0.5f - 0.5f*a1.z;
        float d0w = 0.5f - 0.5f*a0.w, d1w = 0.5f - 0.5f*a1.w;

        int lx = d1x < d0x, ly = d1y < d0y, lz = d1z < d0z, lw = d1w < d0w;
        float4 lab = make_float4((float)lx, (float)ly, (float)lz, (float)lw);

        __stcs(reinterpret_cast<float4*>(out + OFF_LABELS + (size_t)b*NPIX + n0), lab);
        __stcs(reinterpret_cast<float4*>(out + OFF_LABELT + (size_t)b*NPIX + n0), lab);

        float4* outO = reinterpret_cast<float4*>(out + OFF_ONEHOT + (size_t)b*2*NPIX + 2*n0);
        __stcs(outO + 0, make_float4(1.f - lab.x, lab.x, 1.f - lab.y, lab.y));
        __stcs(outO + 1, make_float4(1.f - lab.z, lab.z, 1.f - lab.w, lab.w));

        float4* outD = reinterpret_cast<float4*>(out + OFF_DIST + (size_t)b*2*NPIX + 2*n0);
        __stcs(outD + 0, make_float4(d0x, d1x, d0y, d1y));
        __stcs(outD + 1, make_float4(d0z, d1z, d0w, d1w));

        if (is7) {
            unsigned bx = __ballot_sync(0xffffffffu, lx);
            unsigned by = __ballot_sync(0xffffffffu, ly);
            unsigned bz = __ballot_sync(0xffffffffu, lz);
            unsigned bw = __ballot_sync(0xffffffffu, lw);
            if (lane == 0) g_mask[p4 >> 5] = make_uint4(bx, by, bz, bw);
            __syncthreads();                 // all mask stores of this block issued
            if (t == 0) {
                __threadfence();             // publish mask
                atomicAdd(&g_ready_seg[slot >> 4], 1);   // release this segment
            }
        }
    }

    // ---------------- Phase 2: cooperative F7 masked channel sums ----------
    int ch  = blk & 127;
    int seg = blk >> 7;                    // 0..3 (4096 f4 per segment)

    if (t == 0) {                          // wait only for THIS segment's 16 producers
        volatile int* r = &g_ready_seg[seg];
        while (*r < 16) __nanosleep(128);
    }
    __syncthreads();
    __threadfence();                       // acquire mask

    const float4* Fp = reinterpret_cast<const float4*>(
        F + ((size_t)(BB-1) * C + ch) * NPIX) + seg * 4096;
    const uint4* Mp = g_mask + seg * 128;

    float sa0 = 0.f, sa1 = 0.f, s10 = 0.f, s11 = 0.f;
    #pragma unroll
    for (int i = 0; i < 16; i += 2) {
        int j0 = i*256 + t, j1 = (i+1)*256 + t;   // two independent streams
        float4 f0 = Fp[j0];
        float4 f1 = Fp[j1];
        uint4  m0 = Mp[j0 >> 5];
        uint4  m1 = Mp[j1 >> 5];
        sa0 += (f0.x + f0.y) + (f0.z + f0.w);
        sa1 += (f1.x + f1.y) + (f1.z + f1.w);
        s10 += (msel(m0.x, lane, f0.x) + msel(m0.y, lane, f0.y))
             + (msel(m0.z, lane, f0.z) + msel(m0.w, lane, f0.w));
        s11 += (msel(m1.x, lane, f1.x) + msel(m1.y, lane, f1.y))
             + (msel(m1.z, lane, f1.z) + msel(m1.w, lane, f1.w));
    }
    float sa = sa0 + sa1;
    float s1 = s10 + s11;

    #pragma unroll
    for (int o = 16; o > 0; o >>= 1) {
        sa += __shfl_down_sync(0xffffffffu, sa, o);
        s1 += __shfl_down_sync(0xffffffffu, s1, o);
    }
    if (lane == 0) { wa[wid] = sa; w1[wid] = s1; }
    __syncthreads();
    if (t == 0) {
        float va = 0.f, v1 = 0.f;
        #pragma unroll
        for (int i = 0; i < 8; i++) { va += wa[i]; v1 += w1[i]; }
        g_part[(ch)     * 4 + seg] = va - v1;   // label 0 sum
        g_part[(C + ch) * 4 + seg] = v1;        // label 1 sum
    }

    // ---------------- arrival; last block does the epilogue ----------------
    __syncthreads();
    if (t == 0) {
        __threadfence();
        int old = atomicAdd(&g_arrive, 1);
        s_done = (old == NBLK - 1);
    }
    __syncthreads();
    if (!s_done) return;
    __threadfence();

    // label-1 count via mask popcount (512 uint4 / 256 threads = 2 each)
    {
        uint4 m0 = g_mask[2*t], m1 = g_mask[2*t + 1];
        int c = __popc(m0.x) + __popc(m0.y) + __popc(m0.z) + __popc(m0.w)
              + __popc(m1.x) + __popc(m1.y) + __popc(m1.z) + __popc(m1.w);
        #pragma unroll
        for (int o = 16; o > 0; o >>= 1)
            c += __shfl_down_sync(0xffffffffu, c, o);
        if (lane == 0) wc[wid] = c;
        __syncthreads();
        if (t == 0) {
            int v = 0;
            #pragma unroll
            for (int i = 0; i < 8; i++) v += wc[i];
            s_cnt = v;
        }
        __syncthreads();
    }

    // reduce the 4 seg slots per (k,ch) and write centersIterout
    float sum = 0.f;
    #pragma unroll
    for (int i = 0; i < 4; i++) sum += __ldcg(&g_part[t*4 + i]);

    int k = t >> 7;
    float num = (k ? (float)s_cnt : (float)(NPIX - s_cnt)) + 1.0f;
    float mean = sum / num;
    float ci = sc[t];
    out[OFF_CENTERS + t] = ci + 0.001f * (mean - ci);

    if (t == 0) {                          // reset for next graph replay
        g_arrive = 0;
        g_ready_seg[0] = 0; g_ready_seg[1] = 0;
        g_ready_seg[2] = 0; g_ready_seg[3] = 0;
    }
}

// ---------------------------------------------------------------------------
extern "C" void kernel_launch(void* const* d_in, const int* in_sizes, int n_in,
                              void* d_out, int out_size) {
    const float* F     = (const float*)d_in[0];   // FeatureT [8,128,256,256]
    const float* Cinit = (const float*)d_in[1];   // centerInit [2,128]
    float* out = (float*)d_out;
    (void)in_sizes; (void)n_in; (void)out_size;

    k_all<<<NBLK, 256>>>(F, Cinit, out);
}